// round 2
// baseline (speedup 1.0000x reference)
#include <cuda_runtime.h>
#include <cstdint>

#define N_NODES   50000
#define N_EDGES   1600000
#define N_GRAPHS  128
#define IN_CH     64
#define EDGE_DIM  16
#define HID       64
#define N_CLASSES 10
#define N_LAYERS  5
#define BN_EPS    1e-5f

#define MLP_TN    128           // nodes per MLP block
#define ZT_PAD    132           // padded row length for transposed tiles

// ---------------- scratch (device globals; no allocations allowed) -------
__device__ __align__(16) float g_h[N_NODES * HID];       // node features
__device__ __align__(16) float g_z[N_NODES * HID];       // aggr buffer (kept zeroed between layers)
__device__ __align__(16) float g_zout[N_NODES * HID];    // MLP output
__device__ __align__(16) float g_stats[2 * HID];         // sum, sumsq
__device__ __align__(16) float g_pool[N_GRAPHS * HID];
__device__ __align__(16) float g_cnt[N_GRAPHS];

// ---------------- kernels ------------------------------------------------

// h = x @ Wn + bn ; also zero g_z for layer 0. One thread per (node, channel).
__global__ void k_node_proj(const float* __restrict__ x,
                            const float* __restrict__ Wn,
                            const float* __restrict__ bn) {
    __shared__ float Ws[IN_CH * HID];
    __shared__ float bs[HID];
    int t = threadIdx.x;
    for (int i = t; i < IN_CH * HID; i += blockDim.x) Ws[i] = Wn[i];
    if (t < HID) bs[t] = bn[t];
    __syncthreads();
    int gid = blockIdx.x * blockDim.x + t;
    if (gid >= N_NODES * HID) return;
    int n = gid >> 6, c = gid & 63;
    float acc = bs[c];
    const float* xr = x + (size_t)n * IN_CH;
#pragma unroll 16
    for (int k = 0; k < IN_CH; k++) acc += xr[k] * Ws[k * HID + c];
    g_h[gid] = acc;
    g_z[gid] = 0.0f;
}

// message + scatter: g_z[dst] += relu(h[src] + edge_attr@We + be)
// Edge projection recomputed on the fly (no 409MB g_e buffer).
// 16 threads per edge; each thread owns 4 channels.
// Block 0 also zeroes the BN stats accumulator for this layer.
__global__ void k_msg(const int* __restrict__ ei,
                      const float* __restrict__ ea,
                      const float* __restrict__ We,
                      const float* __restrict__ be) {
    __shared__ float Ws[EDGE_DIM * HID];
    __shared__ float bs[HID];
    int t = threadIdx.x;
    for (int i = t; i < EDGE_DIM * HID; i += blockDim.x) Ws[i] = We[i];
    if (t < HID) bs[t] = be[t];
    if (blockIdx.x == 0 && t < 2 * HID) g_stats[t] = 0.0f;
    __syncthreads();

    int gid = blockIdx.x * blockDim.x + t;            // exact: N_EDGES*16 threads
    int edge = gid >> 4;
    int lane = t & 31;
    int q = lane & 15;                                 // attr index within edge
    int half = lane & 16;                              // which edge in this warp pair
    int c = q * 4;

    // coalesced attr load: warp reads 2 edges * 16 floats = 128B contiguous
    float a = ea[(size_t)edge * EDGE_DIM + q];

    float a0 = bs[c], a1 = bs[c + 1], a2 = bs[c + 2], a3 = bs[c + 3];
#pragma unroll
    for (int k = 0; k < EDGE_DIM; k++) {
        float ak = __shfl_sync(0xffffffffu, a, half | k);
        const float4 w = *reinterpret_cast<const float4*>(&Ws[k * HID + c]);
        a0 += ak * w.x; a1 += ak * w.y; a2 += ak * w.z; a3 += ak * w.w;
    }

    int src = ei[edge];
    int dst = ei[N_EDGES + edge];
    float4 h4 = *reinterpret_cast<const float4*>(&g_h[(size_t)src * HID + c]);
    float m0 = fmaxf(h4.x + a0, 0.0f);
    float m1 = fmaxf(h4.y + a1, 0.0f);
    float m2 = fmaxf(h4.z + a2, 0.0f);
    float m3 = fmaxf(h4.w + a3, 0.0f);
    float* p = &g_z[(size_t)dst * HID + c];
    asm volatile("red.global.add.v4.f32 [%0], {%1, %2, %3, %4};"
                 :: "l"(p), "f"(m0), "f"(m1), "f"(m2), "f"(m3) : "memory");
}

// MLP: zout = relu(((1+eps)h + aggr) @ W1 + b1) @ W2 + b2
// smem-tiled GEMM: 128 nodes/block, 256 threads, 8 nodes x 4 ch per thread.
// Also accumulates per-channel sum/sumsq for BN.
__global__ void k_mlp(const float* __restrict__ W1, const float* __restrict__ b1,
                      const float* __restrict__ W2, const float* __restrict__ b2,
                      const float* __restrict__ eps, int layer) {
    extern __shared__ float sm[];
    float* W1s = sm;                       // 4096
    float* W2s = W1s + HID * HID;          // 4096
    float* zt  = W2s + HID * HID;          // 64 * ZT_PAD (reused for activations)
    float* b1s = zt + HID * ZT_PAD;        // 64
    float* b2s = b1s + HID;                // 64
    float* ssum = b2s + HID;               // 64
    float* ssq  = ssum + HID;              // 64

    int t = threadIdx.x;
    for (int i = t; i < HID * HID; i += 256) { W1s[i] = W1[i]; W2s[i] = W2[i]; }
    if (t < HID) { b1s[t] = b1[t]; b2s[t] = b2[t]; ssum[t] = 0.0f; ssq[t] = 0.0f; }
    float se = 1.0f + eps[layer];
    int node0 = blockIdx.x * MLP_TN;

    // load z tile transposed: zt[k][n] = (1+eps)*h + aggr
    for (int i = t; i < MLP_TN * 16; i += 256) {
        int n = i >> 4, kc = i & 15;
        int node = node0 + n;
        float4 hv = make_float4(0.f, 0.f, 0.f, 0.f);
        float4 av = make_float4(0.f, 0.f, 0.f, 0.f);
        if (node < N_NODES) {
            hv = *reinterpret_cast<const float4*>(&g_h[(size_t)node * HID + kc * 4]);
            av = *reinterpret_cast<const float4*>(&g_z[(size_t)node * HID + kc * 4]);
        }
        zt[(kc * 4 + 0) * ZT_PAD + n] = se * hv.x + av.x;
        zt[(kc * 4 + 1) * ZT_PAD + n] = se * hv.y + av.y;
        zt[(kc * 4 + 2) * ZT_PAD + n] = se * hv.z + av.z;
        zt[(kc * 4 + 3) * ZT_PAD + n] = se * hv.w + av.w;
    }
    __syncthreads();

    int tx = t & 15, ty = t >> 4;
    int cbase = tx * 4, nbase = ty * 8;

    float acc[8][4];
#pragma unroll
    for (int i = 0; i < 8; i++) {
        acc[i][0] = b1s[cbase]; acc[i][1] = b1s[cbase + 1];
        acc[i][2] = b1s[cbase + 2]; acc[i][3] = b1s[cbase + 3];
    }
#pragma unroll 4
    for (int k = 0; k < HID; k++) {
        float4 w = *reinterpret_cast<const float4*>(&W1s[k * HID + cbase]);
        float zv[8];
#pragma unroll
        for (int i = 0; i < 8; i++) zv[i] = zt[k * ZT_PAD + nbase + i];
#pragma unroll
        for (int i = 0; i < 8; i++) {
            acc[i][0] += zv[i] * w.x; acc[i][1] += zv[i] * w.y;
            acc[i][2] += zv[i] * w.z; acc[i][3] += zv[i] * w.w;
        }
    }
    __syncthreads();   // all zt reads done before overwrite
    // write relu(acc) transposed back into zt (as activation tile)
#pragma unroll
    for (int j = 0; j < 4; j++)
#pragma unroll
        for (int i = 0; i < 8; i++)
            zt[(cbase + j) * ZT_PAD + nbase + i] = fmaxf(acc[i][j], 0.0f);
    __syncthreads();

#pragma unroll
    for (int i = 0; i < 8; i++) {
        acc[i][0] = b2s[cbase]; acc[i][1] = b2s[cbase + 1];
        acc[i][2] = b2s[cbase + 2]; acc[i][3] = b2s[cbase + 3];
    }
#pragma unroll 4
    for (int k = 0; k < HID; k++) {
        float4 w = *reinterpret_cast<const float4*>(&W2s[k * HID + cbase]);
        float av[8];
#pragma unroll
        for (int i = 0; i < 8; i++) av[i] = zt[k * ZT_PAD + nbase + i];
#pragma unroll
        for (int i = 0; i < 8; i++) {
            acc[i][0] += av[i] * w.x; acc[i][1] += av[i] * w.y;
            acc[i][2] += av[i] * w.z; acc[i][3] += av[i] * w.w;
        }
    }

    float s[4] = {0.f, 0.f, 0.f, 0.f}, sq[4] = {0.f, 0.f, 0.f, 0.f};
#pragma unroll
    for (int i = 0; i < 8; i++) {
        int node = node0 + nbase + i;
        if (node < N_NODES) {
            float4 o = make_float4(acc[i][0], acc[i][1], acc[i][2], acc[i][3]);
            *reinterpret_cast<float4*>(&g_zout[(size_t)node * HID + cbase]) = o;
#pragma unroll
            for (int j = 0; j < 4; j++) { s[j] += acc[i][j]; sq[j] += acc[i][j] * acc[i][j]; }
        }
    }
#pragma unroll
    for (int j = 0; j < 4; j++) {
        atomicAdd(&ssum[cbase + j], s[j]);
        atomicAdd(&ssq[cbase + j], sq[j]);
    }
    __syncthreads();
    if (t < HID) {
        atomicAdd(&g_stats[t], ssum[t]);
        atomicAdd(&g_stats[HID + t], ssq[t]);
    }
}

// h = relu(gamma*(zout - mu)*inv_std + beta) + h ; also zero g_z for next layer.
// float4 vectorized; BN stats finalized inline.
__global__ void k_bnapply(const float* __restrict__ gamma,
                          const float* __restrict__ beta) {
    int gid = blockIdx.x * blockDim.x + threadIdx.x;
    if (gid >= N_NODES * 16) return;
    int c = (gid & 15) * 4;
    const float invN = 1.0f / (float)N_NODES;
    float4 v = *reinterpret_cast<const float4*>(&g_zout[(size_t)gid * 4]);
    float4 h = *reinterpret_cast<const float4*>(&g_h[(size_t)gid * 4]);
    float r[4] = {v.x, v.y, v.z, v.w};
    float hh[4] = {h.x, h.y, h.z, h.w};
#pragma unroll
    for (int j = 0; j < 4; j++) {
        float mu = g_stats[c + j] * invN;
        float var = g_stats[HID + c + j] * invN - mu * mu;
        float inv = rsqrtf(var + BN_EPS);
        float t = gamma[c + j] * (r[j] - mu) * inv + beta[c + j];
        r[j] = fmaxf(t, 0.0f) + hh[j];
    }
    *reinterpret_cast<float4*>(&g_h[(size_t)gid * 4]) = make_float4(r[0], r[1], r[2], r[3]);
    *reinterpret_cast<float4*>(&g_z[(size_t)gid * 4]) = make_float4(0.f, 0.f, 0.f, 0.f);
}

__global__ void k_pool_zero() {
    int gid = blockIdx.x * blockDim.x + threadIdx.x;
    if (gid < N_GRAPHS * HID) g_pool[gid] = 0.0f;
    if (gid < N_GRAPHS) g_cnt[gid] = 0.0f;
}

__global__ void k_pool(const int* __restrict__ batch) {
    int gid = blockIdx.x * blockDim.x + threadIdx.x;
    if (gid >= N_NODES * 16) return;
    int n = gid >> 4, c = (gid & 15) * 4;
    int b = batch[n];
    float4 h = *reinterpret_cast<const float4*>(&g_h[(size_t)n * HID + c]);
    float* p = &g_pool[b * HID + c];
    asm volatile("red.global.add.v4.f32 [%0], {%1, %2, %3, %4};"
                 :: "l"(p), "f"(h.x), "f"(h.y), "f"(h.z), "f"(h.w) : "memory");
    if ((gid & 15) == 0) {
        asm volatile("red.global.add.f32 [%0], %1;" :: "l"(&g_cnt[b]), "f"(1.0f) : "memory");
    }
}

// classifier: one thread per graph
__global__ void k_cls(const float* __restrict__ W1, const float* __restrict__ b1,
                      const float* __restrict__ W2, const float* __restrict__ b2,
                      float* __restrict__ out) {
    int g = threadIdx.x;
    if (g >= N_GRAPHS) return;
    float cnt = fmaxf(g_cnt[g], 1.0f);
    float inv = 1.0f / cnt;
    float pr[HID];
#pragma unroll
    for (int k = 0; k < HID; k++) pr[k] = g_pool[g * HID + k] * inv;
    float a[HID];
#pragma unroll 4
    for (int j = 0; j < HID; j++) {
        float acc = b1[j];
        for (int k = 0; k < HID; k++) acc += pr[k] * W1[k * HID + j];
        a[j] = fmaxf(acc, 0.0f);
    }
#pragma unroll
    for (int j = 0; j < N_CLASSES; j++) {
        float acc = b2[j];
#pragma unroll 8
        for (int k = 0; k < HID; k++) acc += a[k] * W2[k * N_CLASSES + j];
        float prob = 1.0f / (1.0f + expf(-acc));
        float pred = (prob > 0.5f) ? 1.0f : 0.0f;
        int idx = g * N_CLASSES + j;
        out[idx] = acc;
        out[N_GRAPHS * N_CLASSES + idx] = prob;
        out[2 * N_GRAPHS * N_CLASSES + idx] = pred;
        out[3 * N_GRAPHS * N_CLASSES + idx] = pred;
    }
}

// ---------------- launch --------------------------------------------------
extern "C" void kernel_launch(void* const* d_in, const int* in_sizes, int n_in,
                              void* d_out, int out_size) {
    const float* x      = (const float*)d_in[0];
    const int*   ei     = (const int*)  d_in[1];
    const int*   batch  = (const int*)  d_in[2];
    const float* ea     = (const float*)d_in[3];
    const float* Wn     = (const float*)d_in[4];
    const float* bn     = (const float*)d_in[5];
    const float* We     = (const float*)d_in[6];
    const float* be     = (const float*)d_in[7];
    const float* eps    = (const float*)d_in[8];
    const float* mlp_W1 = (const float*)d_in[9];
    const float* mlp_b1 = (const float*)d_in[10];
    const float* mlp_W2 = (const float*)d_in[11];
    const float* mlp_b2 = (const float*)d_in[12];
    const float* bn_g   = (const float*)d_in[13];
    const float* bn_b   = (const float*)d_in[14];
    const float* cls_W1 = (const float*)d_in[15];
    const float* cls_b1 = (const float*)d_in[16];
    const float* cls_W2 = (const float*)d_in[17];
    const float* cls_b2 = (const float*)d_in[18];
    float* out = (float*)d_out;

    const int TPB = 256;
    const int node_blocks  = (N_NODES * HID + TPB - 1) / TPB;   // 12500
    const int node4_blocks = (N_NODES * 16 + TPB - 1) / TPB;    // 3125
    const int edge_blocks  = (N_EDGES * 16) / TPB;              // 100000
    const int mlp_blocks   = (N_NODES + MLP_TN - 1) / MLP_TN;   // 391
    const int mlp_smem     = (2 * HID * HID + HID * ZT_PAD + 4 * HID) * sizeof(float);

    static bool attr_set = false;
    if (!attr_set) {
        cudaFuncSetAttribute(k_mlp, cudaFuncAttributeMaxDynamicSharedMemorySize, mlp_smem);
        attr_set = true;
    }

    k_node_proj<<<node_blocks, TPB>>>(x, Wn, bn);

    for (int l = 0; l < N_LAYERS; l++) {
        k_msg<<<edge_blocks, TPB>>>(ei, ea, We, be);
        k_mlp<<<mlp_blocks, TPB, mlp_smem>>>(mlp_W1 + l * HID * HID, mlp_b1 + l * HID,
                                             mlp_W2 + l * HID * HID, mlp_b2 + l * HID,
                                             eps, l);
        k_bnapply<<<node4_blocks, TPB>>>(bn_g + l * HID, bn_b + l * HID);
    }

    k_pool_zero<<<(N_GRAPHS * HID + TPB - 1) / TPB, TPB>>>();
    k_pool<<<node4_blocks, TPB>>>(batch);
    k_cls<<<1, 128>>>(cls_W1, cls_b1, cls_W2, cls_b2, out);
}

// round 3
// speedup vs baseline: 1.6613x; 1.6613x over previous
#include <cuda_runtime.h>
#include <cuda_fp16.h>
#include <cstdint>

#define N_NODES   50000
#define N_EDGES   1600000
#define N_GRAPHS  128
#define IN_CH     64
#define EDGE_DIM  16
#define HID       64
#define N_CLASSES 10
#define N_LAYERS  5
#define BN_EPS    1e-5f

#define MLP_TN    128
#define ZT_PAD    132

// ---------------- scratch (device globals) --------------------------------
__device__ __align__(16) float  g_h[N_NODES * HID];
__device__ __align__(16) float  g_z[N_NODES * HID];
__device__ __align__(16) float  g_zout[N_NODES * HID];
__device__ __align__(16) __half g_e16[(size_t)N_EDGES * HID];   // 205MB fp16 edge proj
__device__ __align__(16) float  g_stats[2 * HID];
__device__ __align__(16) float  g_pool[N_GRAPHS * HID];
__device__ __align__(16) float  g_cnt[N_GRAPHS];
// CSR by dst
__device__ int  g_deg[N_NODES];
__device__ int  g_rowptr[N_NODES + 1];
__device__ int  g_cursor[N_NODES];
__device__ __align__(8) int2 g_pair[N_EDGES];   // (src, edge_id) per CSR slot

// ---------------- projections ---------------------------------------------

// h = x @ Wn + bn ; also zero g_deg. One thread per (node, channel).
__global__ void k_node_proj(const float* __restrict__ x,
                            const float* __restrict__ Wn,
                            const float* __restrict__ bn) {
    __shared__ float Ws[IN_CH * HID];
    __shared__ float bs[HID];
    int t = threadIdx.x;
    for (int i = t; i < IN_CH * HID; i += blockDim.x) Ws[i] = Wn[i];
    if (t < HID) bs[t] = bn[t];
    __syncthreads();
    int gid = blockIdx.x * blockDim.x + t;
    if (gid < N_NODES) g_deg[gid] = 0;
    if (gid >= N_NODES * HID) return;
    int n = gid >> 6, c = gid & 63;
    float acc = bs[c];
    const float* xr = x + (size_t)n * IN_CH;
#pragma unroll 16
    for (int k = 0; k < IN_CH; k++) acc += xr[k] * Ws[k * HID + c];
    g_h[gid] = acc;
}

// e = edge_attr @ We + be -> fp16. One thread per (edge, 4 channels).
__global__ void k_edge_proj(const float* __restrict__ ea,
                            const float* __restrict__ We,
                            const float* __restrict__ be) {
    __shared__ float Ws[EDGE_DIM * HID];
    __shared__ float bs[HID];
    int t = threadIdx.x;
    for (int i = t; i < EDGE_DIM * HID; i += blockDim.x) Ws[i] = We[i];
    if (t < HID) bs[t] = be[t];
    __syncthreads();
    int gid = blockIdx.x * blockDim.x + t;
    if (gid >= N_EDGES * 16) return;
    int edge = gid >> 4, q = gid & 15;
    int c = q * 4;
    float a0 = bs[c], a1 = bs[c + 1], a2 = bs[c + 2], a3 = bs[c + 3];
    const float* er = ea + (size_t)edge * EDGE_DIM;
#pragma unroll
    for (int k = 0; k < EDGE_DIM; k++) {
        float v = er[k];
        const float4 w = *reinterpret_cast<const float4*>(&Ws[k * HID + c]);
        a0 += v * w.x; a1 += v * w.y; a2 += v * w.z; a3 += v * w.w;
    }
    __half2 p01 = __floats2half2_rn(a0, a1);
    __half2 p23 = __floats2half2_rn(a2, a3);
    uint2 pk;
    pk.x = *reinterpret_cast<unsigned*>(&p01);
    pk.y = *reinterpret_cast<unsigned*>(&p23);
    *reinterpret_cast<uint2*>(&g_e16[(size_t)edge * HID + c]) = pk;
}

// ---------------- CSR build ------------------------------------------------

__global__ void k_hist(const int* __restrict__ ei) {
    int e = blockIdx.x * blockDim.x + threadIdx.x;
    if (e >= N_EDGES) return;
    atomicAdd(&g_deg[ei[N_EDGES + e]], 1);
}

// single-block exclusive scan of g_deg -> g_rowptr, g_cursor
__global__ void k_scan() {
    __shared__ int sums[1024];
    const int CH = (N_NODES + 1023) / 1024;   // 49
    int t = threadIdx.x;
    int base = t * CH;
    int s = 0;
#pragma unroll 7
    for (int i = 0; i < CH; i++) {
        int idx = base + i;
        s += (idx < N_NODES) ? g_deg[idx] : 0;
    }
    sums[t] = s;
    __syncthreads();
    for (int off = 1; off < 1024; off <<= 1) {
        int v = (t >= off) ? sums[t - off] : 0;
        __syncthreads();
        sums[t] += v;
        __syncthreads();
    }
    int run = (t > 0) ? sums[t - 1] : 0;
#pragma unroll 7
    for (int i = 0; i < CH; i++) {
        int idx = base + i;
        if (idx < N_NODES) {
            g_rowptr[idx] = run;
            g_cursor[idx] = run;
            run += g_deg[idx];
        }
    }
    if (t == 1023) g_rowptr[N_NODES] = sums[1023];
}

__global__ void k_scatter(const int* __restrict__ ei) {
    int e = blockIdx.x * blockDim.x + threadIdx.x;
    if (e >= N_EDGES) return;
    int src = ei[e];
    int dst = ei[N_EDGES + e];
    int pos = atomicAdd(&g_cursor[dst], 1);
    g_pair[pos] = make_int2(src, e);
}

// ---------------- per-layer kernels ----------------------------------------

// z[n] = (1+eps)*h[n] + sum_{j in row(n)} relu(h[src_j] + e_j)
// 16 threads per node, each owns 4 channels. No atomics.
__global__ void k_gather(const float* __restrict__ eps, int layer) {
    int t = threadIdx.x;
    if (blockIdx.x == 0 && t < 2 * HID) g_stats[t] = 0.0f;
    int gid = blockIdx.x * blockDim.x + t;
    if (gid >= N_NODES * 16) return;
    int node = gid >> 4;
    int c = (gid & 15) * 4;
    int j = g_rowptr[node];
    int end = g_rowptr[node + 1];
    float a0 = 0.f, a1 = 0.f, a2 = 0.f, a3 = 0.f;
    if (j < end) {
        int2 pr = g_pair[j];
        for (; j < end; ) {
            int2 cur = pr;
            ++j;
            if (j < end) pr = g_pair[j];               // prefetch next
            float4 h4 = *reinterpret_cast<const float4*>(&g_h[(size_t)cur.x * HID + c]);
            uint2 ev = *reinterpret_cast<const uint2*>(&g_e16[(size_t)cur.y * HID + c]);
            float2 f01 = __half22float2(*reinterpret_cast<__half2*>(&ev.x));
            float2 f23 = __half22float2(*reinterpret_cast<__half2*>(&ev.y));
            a0 += fmaxf(h4.x + f01.x, 0.f);
            a1 += fmaxf(h4.y + f01.y, 0.f);
            a2 += fmaxf(h4.z + f23.x, 0.f);
            a3 += fmaxf(h4.w + f23.y, 0.f);
        }
    }
    float se = 1.0f + eps[layer];
    float4 hv = *reinterpret_cast<const float4*>(&g_h[(size_t)node * HID + c]);
    float4 z = make_float4(se * hv.x + a0, se * hv.y + a1,
                           se * hv.z + a2, se * hv.w + a3);
    *reinterpret_cast<float4*>(&g_z[(size_t)node * HID + c]) = z;
}

// MLP: zout = relu(z @ W1 + b1) @ W2 + b2 ; accumulates BN sum/sumsq.
// 128 nodes/block, 256 threads, 8 nodes x 4 ch per thread, float4 smem loads.
__global__ void k_mlp(const float* __restrict__ W1, const float* __restrict__ b1,
                      const float* __restrict__ W2, const float* __restrict__ b2) {
    extern __shared__ float sm[];
    float* W1s = sm;
    float* W2s = W1s + HID * HID;
    float* zt  = W2s + HID * HID;          // [HID][ZT_PAD] n-major
    float* b1s = zt + HID * ZT_PAD;
    float* b2s = b1s + HID;
    float* ssum = b2s + HID;
    float* ssq  = ssum + HID;

    int t = threadIdx.x;
    for (int i = t; i < HID * HID; i += 256) { W1s[i] = W1[i]; W2s[i] = W2[i]; }
    if (t < HID) { b1s[t] = b1[t]; b2s[t] = b2[t]; ssum[t] = 0.0f; ssq[t] = 0.0f; }
    int node0 = blockIdx.x * MLP_TN;

    // load z tile transposed: zt[k][n]
    for (int i = t; i < MLP_TN * 16; i += 256) {
        int n = i >> 4, kc = i & 15;
        int node = node0 + n;
        float4 zv = make_float4(0.f, 0.f, 0.f, 0.f);
        if (node < N_NODES)
            zv = *reinterpret_cast<const float4*>(&g_z[(size_t)node * HID + kc * 4]);
        zt[(kc * 4 + 0) * ZT_PAD + n] = zv.x;
        zt[(kc * 4 + 1) * ZT_PAD + n] = zv.y;
        zt[(kc * 4 + 2) * ZT_PAD + n] = zv.z;
        zt[(kc * 4 + 3) * ZT_PAD + n] = zv.w;
    }
    __syncthreads();

    int tx = t & 15, ty = t >> 4;
    int cbase = tx * 4, nbase = ty * 8;

    float acc[8][4];
#pragma unroll
    for (int i = 0; i < 8; i++) {
        acc[i][0] = b1s[cbase];     acc[i][1] = b1s[cbase + 1];
        acc[i][2] = b1s[cbase + 2]; acc[i][3] = b1s[cbase + 3];
    }
#pragma unroll 2
    for (int k = 0; k < HID; k++) {
        float4 w   = *reinterpret_cast<const float4*>(&W1s[k * HID + cbase]);
        float4 zv0 = *reinterpret_cast<const float4*>(&zt[k * ZT_PAD + nbase]);
        float4 zv1 = *reinterpret_cast<const float4*>(&zt[k * ZT_PAD + nbase + 4]);
        float zr[8] = {zv0.x, zv0.y, zv0.z, zv0.w, zv1.x, zv1.y, zv1.z, zv1.w};
#pragma unroll
        for (int i = 0; i < 8; i++) {
            acc[i][0] += zr[i] * w.x; acc[i][1] += zr[i] * w.y;
            acc[i][2] += zr[i] * w.z; acc[i][3] += zr[i] * w.w;
        }
    }
    __syncthreads();
#pragma unroll
    for (int j = 0; j < 4; j++)
#pragma unroll
        for (int i = 0; i < 8; i++)
            zt[(cbase + j) * ZT_PAD + nbase + i] = fmaxf(acc[i][j], 0.0f);
    __syncthreads();

#pragma unroll
    for (int i = 0; i < 8; i++) {
        acc[i][0] = b2s[cbase];     acc[i][1] = b2s[cbase + 1];
        acc[i][2] = b2s[cbase + 2]; acc[i][3] = b2s[cbase + 3];
    }
#pragma unroll 2
    for (int k = 0; k < HID; k++) {
        float4 w   = *reinterpret_cast<const float4*>(&W2s[k * HID + cbase]);
        float4 av0 = *reinterpret_cast<const float4*>(&zt[k * ZT_PAD + nbase]);
        float4 av1 = *reinterpret_cast<const float4*>(&zt[k * ZT_PAD + nbase + 4]);
        float ar[8] = {av0.x, av0.y, av0.z, av0.w, av1.x, av1.y, av1.z, av1.w};
#pragma unroll
        for (int i = 0; i < 8; i++) {
            acc[i][0] += ar[i] * w.x; acc[i][1] += ar[i] * w.y;
            acc[i][2] += ar[i] * w.z; acc[i][3] += ar[i] * w.w;
        }
    }

    float s[4] = {0.f, 0.f, 0.f, 0.f}, sq[4] = {0.f, 0.f, 0.f, 0.f};
#pragma unroll
    for (int i = 0; i < 8; i++) {
        int node = node0 + nbase + i;
        if (node < N_NODES) {
            float4 o = make_float4(acc[i][0], acc[i][1], acc[i][2], acc[i][3]);
            *reinterpret_cast<float4*>(&g_zout[(size_t)node * HID + cbase]) = o;
#pragma unroll
            for (int j = 0; j < 4; j++) { s[j] += acc[i][j]; sq[j] += acc[i][j] * acc[i][j]; }
        }
    }
#pragma unroll
    for (int j = 0; j < 4; j++) {
        atomicAdd(&ssum[cbase + j], s[j]);
        atomicAdd(&ssq[cbase + j], sq[j]);
    }
    __syncthreads();
    if (t < HID) {
        atomicAdd(&g_stats[t], ssum[t]);
        atomicAdd(&g_stats[HID + t], ssq[t]);
    }
}

// h = relu(gamma*(zout - mu)*inv_std + beta) + h ; float4 vectorized.
__global__ void k_bnapply(const float* __restrict__ gamma,
                          const float* __restrict__ beta) {
    int gid = blockIdx.x * blockDim.x + threadIdx.x;
    if (gid >= N_NODES * 16) return;
    int c = (gid & 15) * 4;
    const float invN = 1.0f / (float)N_NODES;
    float4 v = *reinterpret_cast<const float4*>(&g_zout[(size_t)gid * 4]);
    float4 h = *reinterpret_cast<const float4*>(&g_h[(size_t)gid * 4]);
    float r[4] = {v.x, v.y, v.z, v.w};
    float hh[4] = {h.x, h.y, h.z, h.w};
#pragma unroll
    for (int j = 0; j < 4; j++) {
        float mu = g_stats[c + j] * invN;
        float var = g_stats[HID + c + j] * invN - mu * mu;
        float inv = rsqrtf(var + BN_EPS);
        float tt = gamma[c + j] * (r[j] - mu) * inv + beta[c + j];
        r[j] = fmaxf(tt, 0.0f) + hh[j];
    }
    *reinterpret_cast<float4*>(&g_h[(size_t)gid * 4]) = make_float4(r[0], r[1], r[2], r[3]);
}

// ---------------- pooling + classifier -------------------------------------

__global__ void k_pool_zero() {
    int gid = blockIdx.x * blockDim.x + threadIdx.x;
    if (gid < N_GRAPHS * HID) g_pool[gid] = 0.0f;
    if (gid < N_GRAPHS) g_cnt[gid] = 0.0f;
}

__global__ void k_pool(const int* __restrict__ batch) {
    int gid = blockIdx.x * blockDim.x + threadIdx.x;
    if (gid >= N_NODES * 16) return;
    int n = gid >> 4, c = (gid & 15) * 4;
    int b = batch[n];
    float4 h = *reinterpret_cast<const float4*>(&g_h[(size_t)n * HID + c]);
    float* p = &g_pool[b * HID + c];
    asm volatile("red.global.add.v4.f32 [%0], {%1, %2, %3, %4};"
                 :: "l"(p), "f"(h.x), "f"(h.y), "f"(h.z), "f"(h.w) : "memory");
    if ((gid & 15) == 0)
        asm volatile("red.global.add.f32 [%0], %1;" :: "l"(&g_cnt[b]), "f"(1.0f) : "memory");
}

__global__ void k_cls(const float* __restrict__ W1, const float* __restrict__ b1,
                      const float* __restrict__ W2, const float* __restrict__ b2,
                      float* __restrict__ out) {
    int g = threadIdx.x;
    if (g >= N_GRAPHS) return;
    float cnt = fmaxf(g_cnt[g], 1.0f);
    float inv = 1.0f / cnt;
    float pr[HID];
#pragma unroll
    for (int k = 0; k < HID; k++) pr[k] = g_pool[g * HID + k] * inv;
    float a[HID];
#pragma unroll 4
    for (int j = 0; j < HID; j++) {
        float acc = b1[j];
        for (int k = 0; k < HID; k++) acc += pr[k] * W1[k * HID + j];
        a[j] = fmaxf(acc, 0.0f);
    }
#pragma unroll
    for (int j = 0; j < N_CLASSES; j++) {
        float acc = b2[j];
#pragma unroll 8
        for (int k = 0; k < HID; k++) acc += a[k] * W2[k * N_CLASSES + j];
        float prob = 1.0f / (1.0f + expf(-acc));
        float pred = (prob > 0.5f) ? 1.0f : 0.0f;
        int idx = g * N_CLASSES + j;
        out[idx] = acc;
        out[N_GRAPHS * N_CLASSES + idx] = prob;
        out[2 * N_GRAPHS * N_CLASSES + idx] = pred;
        out[3 * N_GRAPHS * N_CLASSES + idx] = pred;
    }
}

// ---------------- launch --------------------------------------------------
extern "C" void kernel_launch(void* const* d_in, const int* in_sizes, int n_in,
                              void* d_out, int out_size) {
    const float* x      = (const float*)d_in[0];
    const int*   ei     = (const int*)  d_in[1];
    const int*   batch  = (const int*)  d_in[2];
    const float* ea     = (const float*)d_in[3];
    const float* Wn     = (const float*)d_in[4];
    const float* bn     = (const float*)d_in[5];
    const float* We     = (const float*)d_in[6];
    const float* be     = (const float*)d_in[7];
    const float* eps    = (const float*)d_in[8];
    const float* mlp_W1 = (const float*)d_in[9];
    const float* mlp_b1 = (const float*)d_in[10];
    const float* mlp_W2 = (const float*)d_in[11];
    const float* mlp_b2 = (const float*)d_in[12];
    const float* bn_g   = (const float*)d_in[13];
    const float* bn_b   = (const float*)d_in[14];
    const float* cls_W1 = (const float*)d_in[15];
    const float* cls_b1 = (const float*)d_in[16];
    const float* cls_W2 = (const float*)d_in[17];
    const float* cls_b2 = (const float*)d_in[18];
    float* out = (float*)d_out;

    const int TPB = 256;
    const int node_blocks  = (N_NODES * HID + TPB - 1) / TPB;   // 12500
    const int node4_blocks = (N_NODES * 16 + TPB - 1) / TPB;    // 3125
    const int edge16_blocks = (N_EDGES * 16) / TPB;             // 100000
    const int edge_blocks  = (N_EDGES + TPB - 1) / TPB;         // 6250
    const int mlp_blocks   = (N_NODES + MLP_TN - 1) / MLP_TN;   // 391
    const int mlp_smem     = (2 * HID * HID + HID * ZT_PAD + 4 * HID) * sizeof(float);

    static bool attr_set = false;
    if (!attr_set) {
        cudaFuncSetAttribute(k_mlp, cudaFuncAttributeMaxDynamicSharedMemorySize, mlp_smem);
        attr_set = true;
    }

    k_node_proj<<<node_blocks, TPB>>>(x, Wn, bn);    // also zeroes g_deg
    k_hist<<<edge_blocks, TPB>>>(ei);
    k_edge_proj<<<edge16_blocks, TPB>>>(ea, We, be);
    k_scan<<<1, 1024>>>();
    k_scatter<<<edge_blocks, TPB>>>(ei);

    for (int l = 0; l < N_LAYERS; l++) {
        k_gather<<<node4_blocks, TPB>>>(eps, l);
        k_mlp<<<mlp_blocks, TPB, mlp_smem>>>(mlp_W1 + l * HID * HID, mlp_b1 + l * HID,
                                             mlp_W2 + l * HID * HID, mlp_b2 + l * HID);
        k_bnapply<<<node4_blocks, TPB>>>(bn_g + l * HID, bn_b + l * HID);
    }

    k_pool_zero<<<(N_GRAPHS * HID + TPB - 1) / TPB, TPB>>>();
    k_pool<<<node4_blocks, TPB>>>(batch);
    k_cls<<<1, 128>>>(cls_W1, cls_b1, cls_W2, cls_b2, out);
}

// round 4
// speedup vs baseline: 1.8630x; 1.1214x over previous
#include <cuda_runtime.h>
#include <cuda_fp16.h>
#include <cstdint>

#define N_NODES   50000
#define N_EDGES   1600000
#define N_GRAPHS  128
#define IN_CH     64
#define EDGE_DIM  16
#define HID       64
#define N_CLASSES 10
#define N_LAYERS  5
#define BN_EPS    1e-5f

#define MLP_TN    128
#define ZT_PAD    132
#define SCAN_CHUNK 256
#define N_CHUNKS  ((N_NODES + SCAN_CHUNK - 1) / SCAN_CHUNK)   // 196

// ---------------- scratch (device globals) --------------------------------
__device__ __align__(16) float  g_h[N_NODES * HID];
__device__ __align__(16) float  g_z[N_NODES * HID];
__device__ __align__(16) float  g_zout[N_NODES * HID];
__device__ __align__(16) __half g_e16[(size_t)N_EDGES * HID];   // fp16 edge proj, CSR order
__device__ __align__(16) float  g_stats[2 * HID];
__device__ __align__(16) float  g_pool[N_GRAPHS * HID];
__device__ __align__(16) float  g_cnt[N_GRAPHS];
// CSR by dst
__device__ int  g_deg[N_NODES];
__device__ int  g_rowptr[N_NODES + 1];
__device__ int  g_cursor[N_NODES];
__device__ int  g_chunk[N_CHUNKS];
__device__ int  g_src[N_EDGES];     // src node per CSR slot
__device__ int  g_epos[N_EDGES];    // CSR slot per original edge id

// ---------------- projections ---------------------------------------------

// h = x @ Wn + bn ; also zero g_deg. One thread per (node, channel).
__global__ void k_node_proj(const float* __restrict__ x,
                            const float* __restrict__ Wn,
                            const float* __restrict__ bn) {
    __shared__ float Ws[IN_CH * HID];
    __shared__ float bs[HID];
    int t = threadIdx.x;
    for (int i = t; i < IN_CH * HID; i += blockDim.x) Ws[i] = Wn[i];
    if (t < HID) bs[t] = bn[t];
    __syncthreads();
    int gid = blockIdx.x * blockDim.x + t;
    if (gid < N_NODES) g_deg[gid] = 0;
    if (gid >= N_NODES * HID) return;
    int n = gid >> 6, c = gid & 63;
    float acc = bs[c];
    const float* xr = x + (size_t)n * IN_CH;
#pragma unroll 16
    for (int k = 0; k < IN_CH; k++) acc += xr[k] * Ws[k * HID + c];
    g_h[gid] = acc;
}

// e = edge_attr @ We + be -> fp16, written in CSR order via g_epos.
__global__ void k_edge_proj(const float* __restrict__ ea,
                            const float* __restrict__ We,
                            const float* __restrict__ be) {
    __shared__ float Ws[EDGE_DIM * HID];
    __shared__ float bs[HID];
    int t = threadIdx.x;
    for (int i = t; i < EDGE_DIM * HID; i += blockDim.x) Ws[i] = We[i];
    if (t < HID) bs[t] = be[t];
    __syncthreads();
    int gid = blockIdx.x * blockDim.x + t;
    if (gid >= N_EDGES * 16) return;
    int edge = gid >> 4, q = gid & 15;
    int c = q * 4;
    float a0 = bs[c], a1 = bs[c + 1], a2 = bs[c + 2], a3 = bs[c + 3];
    const float* er = ea + (size_t)edge * EDGE_DIM;
#pragma unroll
    for (int k = 0; k < EDGE_DIM; k++) {
        float v = er[k];
        const float4 w = *reinterpret_cast<const float4*>(&Ws[k * HID + c]);
        a0 += v * w.x; a1 += v * w.y; a2 += v * w.z; a3 += v * w.w;
    }
    __half2 p01 = __floats2half2_rn(a0, a1);
    __half2 p23 = __floats2half2_rn(a2, a3);
    uint2 pk;
    pk.x = *reinterpret_cast<unsigned*>(&p01);
    pk.y = *reinterpret_cast<unsigned*>(&p23);
    int pos = g_epos[edge];
    *reinterpret_cast<uint2*>(&g_e16[(size_t)pos * HID + c]) = pk;
}

// ---------------- CSR build ------------------------------------------------

__global__ void k_hist(const int* __restrict__ ei) {
    int e = blockIdx.x * blockDim.x + threadIdx.x;
    if (e >= N_EDGES) return;
    atomicAdd(&g_deg[ei[N_EDGES + e]], 1);
}

// phase 1: per-chunk totals
__global__ void k_scan_part() {
    __shared__ int sm[SCAN_CHUNK];
    int t = threadIdx.x;
    int idx = blockIdx.x * SCAN_CHUNK + t;
    int v = (idx < N_NODES) ? g_deg[idx] : 0;
    sm[t] = v;
    __syncthreads();
    for (int off = 128; off > 0; off >>= 1) {
        if (t < off) sm[t] += sm[t + off];
        __syncthreads();
    }
    if (t == 0) g_chunk[blockIdx.x] = sm[0];
}

// phase 2: exclusive scan of chunk totals (1 block)
__global__ void k_scan_top() {
    __shared__ int sm[256];
    int t = threadIdx.x;
    sm[t] = (t < N_CHUNKS) ? g_chunk[t] : 0;
    __syncthreads();
    for (int off = 1; off < 256; off <<= 1) {
        int v = (t >= off) ? sm[t - off] : 0;
        __syncthreads();
        sm[t] += v;
        __syncthreads();
    }
    if (t < N_CHUNKS) g_chunk[t] = (t > 0) ? sm[t - 1] : 0;
    if (t == 0) g_rowptr[N_NODES] = N_EDGES;
}

// phase 3: within-chunk exclusive scan + chunk offset -> rowptr, cursor
__global__ void k_scan_final() {
    __shared__ int sm[SCAN_CHUNK];
    int t = threadIdx.x;
    int idx = blockIdx.x * SCAN_CHUNK + t;
    int v = (idx < N_NODES) ? g_deg[idx] : 0;
    sm[t] = v;
    __syncthreads();
    for (int off = 1; off < SCAN_CHUNK; off <<= 1) {
        int u = (t >= off) ? sm[t - off] : 0;
        __syncthreads();
        sm[t] += u;
        __syncthreads();
    }
    if (idx < N_NODES) {
        int r = g_chunk[blockIdx.x] + sm[t] - v;   // exclusive
        g_rowptr[idx] = r;
        g_cursor[idx] = r;
    }
}

__global__ void k_scatter(const int* __restrict__ ei) {
    int e = blockIdx.x * blockDim.x + threadIdx.x;
    if (e >= N_EDGES) return;
    int src = ei[e];
    int dst = ei[N_EDGES + e];
    int pos = atomicAdd(&g_cursor[dst], 1);
    g_src[pos] = src;
    g_epos[e] = pos;
}

// ---------------- per-layer kernels ----------------------------------------

// z[n] = (1+eps)*h[n] + sum_{j in row(n)} relu(h[src_j] + e_j)
// 16 threads per node, 4 channels each. e reads fully streamed.
__global__ void k_gather(const float* __restrict__ eps, int layer) {
    int t = threadIdx.x;
    if (blockIdx.x == 0 && t < 2 * HID) g_stats[t] = 0.0f;
    int gid = blockIdx.x * blockDim.x + t;
    if (gid >= N_NODES * 16) return;
    int node = gid >> 4;
    int c = (gid & 15) * 4;
    int j = g_rowptr[node];
    int end = g_rowptr[node + 1];
    float a0 = 0.f, a1 = 0.f, a2 = 0.f, a3 = 0.f;
    if (j < end) {
        int src = g_src[j];
        for (; j < end; ) {
            int cur = src;
            uint2 ev = *reinterpret_cast<const uint2*>(&g_e16[(size_t)j * HID + c]);
            ++j;
            if (j < end) src = g_src[j];                 // prefetch next src
            float4 h4 = *reinterpret_cast<const float4*>(&g_h[(size_t)cur * HID + c]);
            float2 f01 = __half22float2(*reinterpret_cast<__half2*>(&ev.x));
            float2 f23 = __half22float2(*reinterpret_cast<__half2*>(&ev.y));
            a0 += fmaxf(h4.x + f01.x, 0.f);
            a1 += fmaxf(h4.y + f01.y, 0.f);
            a2 += fmaxf(h4.z + f23.x, 0.f);
            a3 += fmaxf(h4.w + f23.y, 0.f);
        }
    }
    float se = 1.0f + eps[layer];
    float4 hv = *reinterpret_cast<const float4*>(&g_h[(size_t)node * HID + c]);
    float4 z = make_float4(se * hv.x + a0, se * hv.y + a1,
                           se * hv.z + a2, se * hv.w + a3);
    *reinterpret_cast<float4*>(&g_z[(size_t)node * HID + c]) = z;
}

// MLP: zout = relu(z @ W1 + b1) @ W2 + b2 ; accumulates BN sum/sumsq.
__global__ void k_mlp(const float* __restrict__ W1, const float* __restrict__ b1,
                      const float* __restrict__ W2, const float* __restrict__ b2) {
    extern __shared__ float sm[];
    float* W1s = sm;
    float* W2s = W1s + HID * HID;
    float* zt  = W2s + HID * HID;          // [HID][ZT_PAD] n-major
    float* b1s = zt + HID * ZT_PAD;
    float* b2s = b1s + HID;
    float* ssum = b2s + HID;
    float* ssq  = ssum + HID;

    int t = threadIdx.x;
    for (int i = t; i < HID * HID; i += 256) { W1s[i] = W1[i]; W2s[i] = W2[i]; }
    if (t < HID) { b1s[t] = b1[t]; b2s[t] = b2[t]; ssum[t] = 0.0f; ssq[t] = 0.0f; }
    int node0 = blockIdx.x * MLP_TN;

    for (int i = t; i < MLP_TN * 16; i += 256) {
        int n = i >> 4, kc = i & 15;
        int node = node0 + n;
        float4 zv = make_float4(0.f, 0.f, 0.f, 0.f);
        if (node < N_NODES)
            zv = *reinterpret_cast<const float4*>(&g_z[(size_t)node * HID + kc * 4]);
        zt[(kc * 4 + 0) * ZT_PAD + n] = zv.x;
        zt[(kc * 4 + 1) * ZT_PAD + n] = zv.y;
        zt[(kc * 4 + 2) * ZT_PAD + n] = zv.z;
        zt[(kc * 4 + 3) * ZT_PAD + n] = zv.w;
    }
    __syncthreads();

    int tx = t & 15, ty = t >> 4;
    int cbase = tx * 4, nbase = ty * 8;

    float acc[8][4];
#pragma unroll
    for (int i = 0; i < 8; i++) {
        acc[i][0] = b1s[cbase];     acc[i][1] = b1s[cbase + 1];
        acc[i][2] = b1s[cbase + 2]; acc[i][3] = b1s[cbase + 3];
    }
#pragma unroll 2
    for (int k = 0; k < HID; k++) {
        float4 w   = *reinterpret_cast<const float4*>(&W1s[k * HID + cbase]);
        float4 zv0 = *reinterpret_cast<const float4*>(&zt[k * ZT_PAD + nbase]);
        float4 zv1 = *reinterpret_cast<const float4*>(&zt[k * ZT_PAD + nbase + 4]);
        float zr[8] = {zv0.x, zv0.y, zv0.z, zv0.w, zv1.x, zv1.y, zv1.z, zv1.w};
#pragma unroll
        for (int i = 0; i < 8; i++) {
            acc[i][0] += zr[i] * w.x; acc[i][1] += zr[i] * w.y;
            acc[i][2] += zr[i] * w.z; acc[i][3] += zr[i] * w.w;
        }
    }
    __syncthreads();
#pragma unroll
    for (int j = 0; j < 4; j++)
#pragma unroll
        for (int i = 0; i < 8; i++)
            zt[(cbase + j) * ZT_PAD + nbase + i] = fmaxf(acc[i][j], 0.0f);
    __syncthreads();

#pragma unroll
    for (int i = 0; i < 8; i++) {
        acc[i][0] = b2s[cbase];     acc[i][1] = b2s[cbase + 1];
        acc[i][2] = b2s[cbase + 2]; acc[i][3] = b2s[cbase + 3];
    }
#pragma unroll 2
    for (int k = 0; k < HID; k++) {
        float4 w   = *reinterpret_cast<const float4*>(&W2s[k * HID + cbase]);
        float4 av0 = *reinterpret_cast<const float4*>(&zt[k * ZT_PAD + nbase]);
        float4 av1 = *reinterpret_cast<const float4*>(&zt[k * ZT_PAD + nbase + 4]);
        float ar[8] = {av0.x, av0.y, av0.z, av0.w, av1.x, av1.y, av1.z, av1.w};
#pragma unroll
        for (int i = 0; i < 8; i++) {
            acc[i][0] += ar[i] * w.x; acc[i][1] += ar[i] * w.y;
            acc[i][2] += ar[i] * w.z; acc[i][3] += ar[i] * w.w;
        }
    }

    float s[4] = {0.f, 0.f, 0.f, 0.f}, sq[4] = {0.f, 0.f, 0.f, 0.f};
#pragma unroll
    for (int i = 0; i < 8; i++) {
        int node = node0 + nbase + i;
        if (node < N_NODES) {
            float4 o = make_float4(acc[i][0], acc[i][1], acc[i][2], acc[i][3]);
            *reinterpret_cast<float4*>(&g_zout[(size_t)node * HID + cbase]) = o;
#pragma unroll
            for (int j = 0; j < 4; j++) { s[j] += acc[i][j]; sq[j] += acc[i][j] * acc[i][j]; }
        }
    }
#pragma unroll
    for (int j = 0; j < 4; j++) {
        atomicAdd(&ssum[cbase + j], s[j]);
        atomicAdd(&ssq[cbase + j], sq[j]);
    }
    __syncthreads();
    if (t < HID) {
        atomicAdd(&g_stats[t], ssum[t]);
        atomicAdd(&g_stats[HID + t], ssq[t]);
    }
}

// h = relu(gamma*(zout - mu)*inv_std + beta) + h. If last layer, fuse pooling.
__global__ void k_bnapply(const float* __restrict__ gamma,
                          const float* __restrict__ beta,
                          const int* __restrict__ batch, int do_pool) {
    int gid = blockIdx.x * blockDim.x + threadIdx.x;
    if (gid >= N_NODES * 16) return;
    int c = (gid & 15) * 4;
    const float invN = 1.0f / (float)N_NODES;
    float4 v = *reinterpret_cast<const float4*>(&g_zout[(size_t)gid * 4]);
    float4 h = *reinterpret_cast<const float4*>(&g_h[(size_t)gid * 4]);
    float r[4] = {v.x, v.y, v.z, v.w};
    float hh[4] = {h.x, h.y, h.z, h.w};
#pragma unroll
    for (int j = 0; j < 4; j++) {
        float mu = g_stats[c + j] * invN;
        float var = g_stats[HID + c + j] * invN - mu * mu;
        float inv = rsqrtf(var + BN_EPS);
        float tt = gamma[c + j] * (r[j] - mu) * inv + beta[c + j];
        r[j] = fmaxf(tt, 0.0f) + hh[j];
    }
    *reinterpret_cast<float4*>(&g_h[(size_t)gid * 4]) = make_float4(r[0], r[1], r[2], r[3]);
    if (do_pool) {
        int n = gid >> 4;
        int b = batch[n];
        float* p = &g_pool[b * HID + c];
        asm volatile("red.global.add.v4.f32 [%0], {%1, %2, %3, %4};"
                     :: "l"(p), "f"(r[0]), "f"(r[1]), "f"(r[2]), "f"(r[3]) : "memory");
        if ((gid & 15) == 0)
            asm volatile("red.global.add.f32 [%0], %1;" :: "l"(&g_cnt[b]), "f"(1.0f) : "memory");
    }
}

// ---------------- pooling + classifier -------------------------------------

__global__ void k_pool_zero() {
    int gid = blockIdx.x * blockDim.x + threadIdx.x;
    if (gid < N_GRAPHS * HID) g_pool[gid] = 0.0f;
    if (gid < N_GRAPHS) g_cnt[gid] = 0.0f;
}

// classifier: one block (64 threads) per graph
__global__ void k_cls(const float* __restrict__ W1, const float* __restrict__ b1,
                      const float* __restrict__ W2, const float* __restrict__ b2,
                      float* __restrict__ out) {
    __shared__ float pr[HID];
    __shared__ float aw[HID];
    int g = blockIdx.x;
    int t = threadIdx.x;
    float cnt = fmaxf(g_cnt[g], 1.0f);
    pr[t] = g_pool[g * HID + t] / cnt;
    __syncthreads();
    float acc = b1[t];
#pragma unroll 8
    for (int k = 0; k < HID; k++) acc += pr[k] * W1[k * HID + t];
    aw[t] = fmaxf(acc, 0.0f);
    __syncthreads();
    if (t < N_CLASSES) {
        float o = b2[t];
#pragma unroll 8
        for (int k = 0; k < HID; k++) o += aw[k] * W2[k * N_CLASSES + t];
        float prob = 1.0f / (1.0f + expf(-o));
        float pred = (prob > 0.5f) ? 1.0f : 0.0f;
        int idx = g * N_CLASSES + t;
        out[idx] = o;
        out[N_GRAPHS * N_CLASSES + idx] = prob;
        out[2 * N_GRAPHS * N_CLASSES + idx] = pred;
        out[3 * N_GRAPHS * N_CLASSES + idx] = pred;
    }
}

// ---------------- launch --------------------------------------------------
extern "C" void kernel_launch(void* const* d_in, const int* in_sizes, int n_in,
                              void* d_out, int out_size) {
    const float* x      = (const float*)d_in[0];
    const int*   ei     = (const int*)  d_in[1];
    const int*   batch  = (const int*)  d_in[2];
    const float* ea     = (const float*)d_in[3];
    const float* Wn     = (const float*)d_in[4];
    const float* bn     = (const float*)d_in[5];
    const float* We     = (const float*)d_in[6];
    const float* be     = (const float*)d_in[7];
    const float* eps    = (const float*)d_in[8];
    const float* mlp_W1 = (const float*)d_in[9];
    const float* mlp_b1 = (const float*)d_in[10];
    const float* mlp_W2 = (const float*)d_in[11];
    const float* mlp_b2 = (const float*)d_in[12];
    const float* bn_g   = (const float*)d_in[13];
    const float* bn_b   = (const float*)d_in[14];
    const float* cls_W1 = (const float*)d_in[15];
    const float* cls_b1 = (const float*)d_in[16];
    const float* cls_W2 = (const float*)d_in[17];
    const float* cls_b2 = (const float*)d_in[18];
    float* out = (float*)d_out;

    const int TPB = 256;
    const int node_blocks   = (N_NODES * HID + TPB - 1) / TPB;   // 12500
    const int node4_blocks  = (N_NODES * 16 + TPB - 1) / TPB;    // 3125
    const int edge16_blocks = (N_EDGES * 16) / TPB;              // 100000
    const int edge_blocks   = (N_EDGES + TPB - 1) / TPB;         // 6250
    const int mlp_blocks    = (N_NODES + MLP_TN - 1) / MLP_TN;   // 391
    const int mlp_smem      = (2 * HID * HID + HID * ZT_PAD + 4 * HID) * sizeof(float);

    static bool attr_set = false;
    if (!attr_set) {
        cudaFuncSetAttribute(k_mlp, cudaFuncAttributeMaxDynamicSharedMemorySize, mlp_smem);
        attr_set = true;
    }

    k_node_proj<<<node_blocks, TPB>>>(x, Wn, bn);    // also zeroes g_deg
    k_hist<<<edge_blocks, TPB>>>(ei);
    k_scan_part<<<N_CHUNKS, SCAN_CHUNK>>>();
    k_scan_top<<<1, 256>>>();
    k_scan_final<<<N_CHUNKS, SCAN_CHUNK>>>();
    k_scatter<<<edge_blocks, TPB>>>(ei);
    k_edge_proj<<<edge16_blocks, TPB>>>(ea, We, be);
    k_pool_zero<<<(N_GRAPHS * HID + TPB - 1) / TPB, TPB>>>();

    for (int l = 0; l < N_LAYERS; l++) {
        k_gather<<<node4_blocks, TPB>>>(eps, l);
        k_mlp<<<mlp_blocks, TPB, mlp_smem>>>(mlp_W1 + l * HID * HID, mlp_b1 + l * HID,
                                             mlp_W2 + l * HID * HID, mlp_b2 + l * HID);
        k_bnapply<<<node4_blocks, TPB>>>(bn_g + l * HID, bn_b + l * HID,
                                         batch, (l == N_LAYERS - 1) ? 1 : 0);
    }

    k_cls<<<N_GRAPHS, HID>>>(cls_W1, cls_b1, cls_W2, cls_b2, out);
}

// round 5
// speedup vs baseline: 1.9127x; 1.0267x over previous
#include <cuda_runtime.h>
#include <cuda_fp16.h>
#include <cstdint>

#define N_NODES   50000
#define N_EDGES   1600000
#define N_GRAPHS  128
#define IN_CH     64
#define EDGE_DIM  16
#define HID       64
#define N_CLASSES 10
#define N_LAYERS  5
#define BN_EPS    1e-5f

#define MLP_TN    128
#define ZT_PAD    132
#define SCAN_CHUNK 256
#define N_CHUNKS  ((N_NODES + SCAN_CHUNK - 1) / SCAN_CHUNK)   // 196

// ---------------- scratch (device globals) --------------------------------
__device__ __align__(16) float  g_h[N_NODES * HID];
__device__ __align__(16) __half g_h16[N_NODES * HID];           // fp16 mirror of h
__device__ __align__(16) float  g_z[N_NODES * HID];
__device__ __align__(16) float  g_zout[N_NODES * HID];
__device__ __align__(16) __half g_e16[(size_t)N_EDGES * HID];   // fp16 edge proj, CSR order
__device__ __align__(16) float  g_stats[2 * HID];
__device__ __align__(16) float  g_pool[N_GRAPHS * HID];
__device__ __align__(16) float  g_cnt[N_GRAPHS];
// CSR by dst
__device__ int  g_deg[N_NODES];
__device__ int  g_rowptr[N_NODES + 1];
__device__ int  g_cursor[N_NODES];
__device__ int  g_chunk[N_CHUNKS];
__device__ int  g_src[N_EDGES];     // src node per CSR slot
__device__ int  g_epos[N_EDGES];    // CSR slot per original edge id

// ---------------- projections ---------------------------------------------

// h = x @ Wn + bn ; writes fp32 + fp16; zeroes g_deg.
__global__ void k_node_proj(const float* __restrict__ x,
                            const float* __restrict__ Wn,
                            const float* __restrict__ bn) {
    __shared__ float Ws[IN_CH * HID];
    __shared__ float bs[HID];
    int t = threadIdx.x;
    for (int i = t; i < IN_CH * HID; i += blockDim.x) Ws[i] = Wn[i];
    if (t < HID) bs[t] = bn[t];
    __syncthreads();
    int gid = blockIdx.x * blockDim.x + t;
    if (gid < N_NODES) g_deg[gid] = 0;
    if (gid >= N_NODES * HID) return;
    int n = gid >> 6, c = gid & 63;
    float acc = bs[c];
    const float* xr = x + (size_t)n * IN_CH;
#pragma unroll 16
    for (int k = 0; k < IN_CH; k++) acc += xr[k] * Ws[k * HID + c];
    g_h[gid] = acc;
    g_h16[gid] = __float2half(acc);
}

// e = edge_attr @ We + be -> fp16, written in CSR order via g_epos.
__global__ void k_edge_proj(const float* __restrict__ ea,
                            const float* __restrict__ We,
                            const float* __restrict__ be) {
    __shared__ float Ws[EDGE_DIM * HID];
    __shared__ float bs[HID];
    int t = threadIdx.x;
    for (int i = t; i < EDGE_DIM * HID; i += blockDim.x) Ws[i] = We[i];
    if (t < HID) bs[t] = be[t];
    __syncthreads();
    int gid = blockIdx.x * blockDim.x + t;
    if (gid >= N_EDGES * 16) return;
    int edge = gid >> 4, q = gid & 15;
    int c = q * 4;
    float a0 = bs[c], a1 = bs[c + 1], a2 = bs[c + 2], a3 = bs[c + 3];
    const float* er = ea + (size_t)edge * EDGE_DIM;
#pragma unroll
    for (int k = 0; k < EDGE_DIM; k++) {
        float v = er[k];
        const float4 w = *reinterpret_cast<const float4*>(&Ws[k * HID + c]);
        a0 += v * w.x; a1 += v * w.y; a2 += v * w.z; a3 += v * w.w;
    }
    __half2 p01 = __floats2half2_rn(a0, a1);
    __half2 p23 = __floats2half2_rn(a2, a3);
    uint2 pk;
    pk.x = *reinterpret_cast<unsigned*>(&p01);
    pk.y = *reinterpret_cast<unsigned*>(&p23);
    int pos = g_epos[edge];
    *reinterpret_cast<uint2*>(&g_e16[(size_t)pos * HID + c]) = pk;
}

// ---------------- CSR build ------------------------------------------------

__global__ void k_hist(const int* __restrict__ ei) {
    int e = blockIdx.x * blockDim.x + threadIdx.x;
    if (e >= N_EDGES) return;
    atomicAdd(&g_deg[ei[N_EDGES + e]], 1);
}

__global__ void k_scan_part() {
    __shared__ int sm[SCAN_CHUNK];
    int t = threadIdx.x;
    int idx = blockIdx.x * SCAN_CHUNK + t;
    int v = (idx < N_NODES) ? g_deg[idx] : 0;
    sm[t] = v;
    __syncthreads();
    for (int off = 128; off > 0; off >>= 1) {
        if (t < off) sm[t] += sm[t + off];
        __syncthreads();
    }
    if (t == 0) g_chunk[blockIdx.x] = sm[0];
}

__global__ void k_scan_top() {
    __shared__ int sm[256];
    int t = threadIdx.x;
    sm[t] = (t < N_CHUNKS) ? g_chunk[t] : 0;
    __syncthreads();
    for (int off = 1; off < 256; off <<= 1) {
        int v = (t >= off) ? sm[t - off] : 0;
        __syncthreads();
        sm[t] += v;
        __syncthreads();
    }
    if (t < N_CHUNKS) g_chunk[t] = (t > 0) ? sm[t - 1] : 0;
    if (t == 0) g_rowptr[N_NODES] = N_EDGES;
}

__global__ void k_scan_final() {
    __shared__ int sm[SCAN_CHUNK];
    int t = threadIdx.x;
    int idx = blockIdx.x * SCAN_CHUNK + t;
    int v = (idx < N_NODES) ? g_deg[idx] : 0;
    sm[t] = v;
    __syncthreads();
    for (int off = 1; off < SCAN_CHUNK; off <<= 1) {
        int u = (t >= off) ? sm[t - off] : 0;
        __syncthreads();
        sm[t] += u;
        __syncthreads();
    }
    if (idx < N_NODES) {
        int r = g_chunk[blockIdx.x] + sm[t] - v;   // exclusive
        g_rowptr[idx] = r;
        g_cursor[idx] = r;
    }
}

__global__ void k_scatter(const int* __restrict__ ei) {
    int e = blockIdx.x * blockDim.x + threadIdx.x;
    if (e >= N_EDGES) return;
    int src = ei[e];
    int dst = ei[N_EDGES + e];
    int pos = atomicAdd(&g_cursor[dst], 1);
    g_src[pos] = src;
    g_epos[e] = pos;
}

// ---------------- per-layer kernels ----------------------------------------

// z[n] = (1+eps)*h[n] + sum_j relu(h16[src_j] + e16_j)
// 16 threads per node, 4 channels each; half2 math, fp32 accumulation.
__global__ void k_gather(const float* __restrict__ eps, int layer) {
    int t = threadIdx.x;
    if (blockIdx.x == 0 && t < 2 * HID) g_stats[t] = 0.0f;
    int gid = blockIdx.x * blockDim.x + t;
    if (gid >= N_NODES * 16) return;
    int node = gid >> 4;
    int c = (gid & 15) * 4;
    int j = g_rowptr[node];
    int end = g_rowptr[node + 1];
    float a0 = 0.f, a1 = 0.f, a2 = 0.f, a3 = 0.f;
    const __half2 zero2 = __float2half2_rn(0.0f);
    if (j < end) {
        int src = g_src[j];
        for (; j < end; ) {
            int cur = src;
            uint2 ev = *reinterpret_cast<const uint2*>(&g_e16[(size_t)j * HID + c]);
            ++j;
            if (j < end) src = g_src[j];                 // prefetch next src
            uint2 hv = *reinterpret_cast<const uint2*>(&g_h16[(size_t)cur * HID + c]);
            __half2 e01 = *reinterpret_cast<__half2*>(&ev.x);
            __half2 e23 = *reinterpret_cast<__half2*>(&ev.y);
            __half2 h01 = *reinterpret_cast<__half2*>(&hv.x);
            __half2 h23 = *reinterpret_cast<__half2*>(&hv.y);
            __half2 m01 = __hmax2(__hadd2(h01, e01), zero2);
            __half2 m23 = __hmax2(__hadd2(h23, e23), zero2);
            float2 f01 = __half22float2(m01);
            float2 f23 = __half22float2(m23);
            a0 += f01.x; a1 += f01.y; a2 += f23.x; a3 += f23.y;
        }
    }
    float se = 1.0f + eps[layer];
    float4 hv = *reinterpret_cast<const float4*>(&g_h[(size_t)node * HID + c]);
    float4 z = make_float4(se * hv.x + a0, se * hv.y + a1,
                           se * hv.z + a2, se * hv.w + a3);
    *reinterpret_cast<float4*>(&g_z[(size_t)node * HID + c]) = z;
}

// MLP: zout = relu(z @ W1 + b1) @ W2 + b2 ; accumulates BN sum/sumsq.
__global__ void k_mlp(const float* __restrict__ W1, const float* __restrict__ b1,
                      const float* __restrict__ W2, const float* __restrict__ b2) {
    extern __shared__ float sm[];
    float* W1s = sm;
    float* W2s = W1s + HID * HID;
    float* zt  = W2s + HID * HID;          // [HID][ZT_PAD] n-major
    float* b1s = zt + HID * ZT_PAD;
    float* b2s = b1s + HID;
    float* ssum = b2s + HID;
    float* ssq  = ssum + HID;

    int t = threadIdx.x;
    for (int i = t; i < HID * HID; i += 256) { W1s[i] = W1[i]; W2s[i] = W2[i]; }
    if (t < HID) { b1s[t] = b1[t]; b2s[t] = b2[t]; ssum[t] = 0.0f; ssq[t] = 0.0f; }
    int node0 = blockIdx.x * MLP_TN;

    for (int i = t; i < MLP_TN * 16; i += 256) {
        int n = i >> 4, kc = i & 15;
        int node = node0 + n;
        float4 zv = make_float4(0.f, 0.f, 0.f, 0.f);
        if (node < N_NODES)
            zv = *reinterpret_cast<const float4*>(&g_z[(size_t)node * HID + kc * 4]);
        zt[(kc * 4 + 0) * ZT_PAD + n] = zv.x;
        zt[(kc * 4 + 1) * ZT_PAD + n] = zv.y;
        zt[(kc * 4 + 2) * ZT_PAD + n] = zv.z;
        zt[(kc * 4 + 3) * ZT_PAD + n] = zv.w;
    }
    __syncthreads();

    int tx = t & 15, ty = t >> 4;
    int cbase = tx * 4, nbase = ty * 8;

    float acc[8][4];
#pragma unroll
    for (int i = 0; i < 8; i++) {
        acc[i][0] = b1s[cbase];     acc[i][1] = b1s[cbase + 1];
        acc[i][2] = b1s[cbase + 2]; acc[i][3] = b1s[cbase + 3];
    }
#pragma unroll 2
    for (int k = 0; k < HID; k++) {
        float4 w   = *reinterpret_cast<const float4*>(&W1s[k * HID + cbase]);
        float4 zv0 = *reinterpret_cast<const float4*>(&zt[k * ZT_PAD + nbase]);
        float4 zv1 = *reinterpret_cast<const float4*>(&zt[k * ZT_PAD + nbase + 4]);
        float zr[8] = {zv0.x, zv0.y, zv0.z, zv0.w, zv1.x, zv1.y, zv1.z, zv1.w};
#pragma unroll
        for (int i = 0; i < 8; i++) {
            acc[i][0] += zr[i] * w.x; acc[i][1] += zr[i] * w.y;
            acc[i][2] += zr[i] * w.z; acc[i][3] += zr[i] * w.w;
        }
    }
    __syncthreads();
#pragma unroll
    for (int j = 0; j < 4; j++)
#pragma unroll
        for (int i = 0; i < 8; i++)
            zt[(cbase + j) * ZT_PAD + nbase + i] = fmaxf(acc[i][j], 0.0f);
    __syncthreads();

#pragma unroll
    for (int i = 0; i < 8; i++) {
        acc[i][0] = b2s[cbase];     acc[i][1] = b2s[cbase + 1];
        acc[i][2] = b2s[cbase + 2]; acc[i][3] = b2s[cbase + 3];
    }
#pragma unroll 2
    for (int k = 0; k < HID; k++) {
        float4 w   = *reinterpret_cast<const float4*>(&W2s[k * HID + cbase]);
        float4 av0 = *reinterpret_cast<const float4*>(&zt[k * ZT_PAD + nbase]);
        float4 av1 = *reinterpret_cast<const float4*>(&zt[k * ZT_PAD + nbase + 4]);
        float ar[8] = {av0.x, av0.y, av0.z, av0.w, av1.x, av1.y, av1.z, av1.w};
#pragma unroll
        for (int i = 0; i < 8; i++) {
            acc[i][0] += ar[i] * w.x; acc[i][1] += ar[i] * w.y;
            acc[i][2] += ar[i] * w.z; acc[i][3] += ar[i] * w.w;
        }
    }

    float s[4] = {0.f, 0.f, 0.f, 0.f}, sq[4] = {0.f, 0.f, 0.f, 0.f};
#pragma unroll
    for (int i = 0; i < 8; i++) {
        int node = node0 + nbase + i;
        if (node < N_NODES) {
            float4 o = make_float4(acc[i][0], acc[i][1], acc[i][2], acc[i][3]);
            *reinterpret_cast<float4*>(&g_zout[(size_t)node * HID + cbase]) = o;
#pragma unroll
            for (int j = 0; j < 4; j++) { s[j] += acc[i][j]; sq[j] += acc[i][j] * acc[i][j]; }
        }
    }
#pragma unroll
    for (int j = 0; j < 4; j++) {
        atomicAdd(&ssum[cbase + j], s[j]);
        atomicAdd(&ssq[cbase + j], sq[j]);
    }
    __syncthreads();
    if (t < HID) {
        atomicAdd(&g_stats[t], ssum[t]);
        atomicAdd(&g_stats[HID + t], ssq[t]);
    }
}

// h = relu(gamma*(zout - mu)*inv_std + beta) + h ; writes fp32 + fp16 h.
// If last layer, fuse pooling.
__global__ void k_bnapply(const float* __restrict__ gamma,
                          const float* __restrict__ beta,
                          const int* __restrict__ batch, int do_pool) {
    int gid = blockIdx.x * blockDim.x + threadIdx.x;
    if (gid >= N_NODES * 16) return;
    int c = (gid & 15) * 4;
    const float invN = 1.0f / (float)N_NODES;
    float4 v = *reinterpret_cast<const float4*>(&g_zout[(size_t)gid * 4]);
    float4 h = *reinterpret_cast<const float4*>(&g_h[(size_t)gid * 4]);
    float r[4] = {v.x, v.y, v.z, v.w};
    float hh[4] = {h.x, h.y, h.z, h.w};
#pragma unroll
    for (int j = 0; j < 4; j++) {
        float mu = g_stats[c + j] * invN;
        float var = g_stats[HID + c + j] * invN - mu * mu;
        float inv = rsqrtf(var + BN_EPS);
        float tt = gamma[c + j] * (r[j] - mu) * inv + beta[c + j];
        r[j] = fmaxf(tt, 0.0f) + hh[j];
    }
    *reinterpret_cast<float4*>(&g_h[(size_t)gid * 4]) = make_float4(r[0], r[1], r[2], r[3]);
    __half2 p01 = __floats2half2_rn(r[0], r[1]);
    __half2 p23 = __floats2half2_rn(r[2], r[3]);
    uint2 pk;
    pk.x = *reinterpret_cast<unsigned*>(&p01);
    pk.y = *reinterpret_cast<unsigned*>(&p23);
    *reinterpret_cast<uint2*>(&g_h16[(size_t)gid * 4]) = pk;
    if (do_pool) {
        int n = gid >> 4;
        int b = batch[n];
        float* p = &g_pool[b * HID + c];
        asm volatile("red.global.add.v4.f32 [%0], {%1, %2, %3, %4};"
                     :: "l"(p), "f"(r[0]), "f"(r[1]), "f"(r[2]), "f"(r[3]) : "memory");
        if ((gid & 15) == 0)
            asm volatile("red.global.add.f32 [%0], %1;" :: "l"(&g_cnt[b]), "f"(1.0f) : "memory");
    }
}

// ---------------- pooling + classifier -------------------------------------

__global__ void k_pool_zero() {
    int gid = blockIdx.x * blockDim.x + threadIdx.x;
    if (gid < N_GRAPHS * HID) g_pool[gid] = 0.0f;
    if (gid < N_GRAPHS) g_cnt[gid] = 0.0f;
}

// classifier: one block (64 threads) per graph
__global__ void k_cls(const float* __restrict__ W1, const float* __restrict__ b1,
                      const float* __restrict__ W2, const float* __restrict__ b2,
                      float* __restrict__ out) {
    __shared__ float pr[HID];
    __shared__ float aw[HID];
    int g = blockIdx.x;
    int t = threadIdx.x;
    float cnt = fmaxf(g_cnt[g], 1.0f);
    pr[t] = g_pool[g * HID + t] / cnt;
    __syncthreads();
    float acc = b1[t];
#pragma unroll 8
    for (int k = 0; k < HID; k++) acc += pr[k] * W1[k * HID + t];
    aw[t] = fmaxf(acc, 0.0f);
    __syncthreads();
    if (t < N_CLASSES) {
        float o = b2[t];
#pragma unroll 8
        for (int k = 0; k < HID; k++) o += aw[k] * W2[k * N_CLASSES + t];
        float prob = 1.0f / (1.0f + expf(-o));
        float pred = (prob > 0.5f) ? 1.0f : 0.0f;
        int idx = g * N_CLASSES + t;
        out[idx] = o;
        out[N_GRAPHS * N_CLASSES + idx] = prob;
        out[2 * N_GRAPHS * N_CLASSES + idx] = pred;
        out[3 * N_GRAPHS * N_CLASSES + idx] = pred;
    }
}

// ---------------- launch --------------------------------------------------
extern "C" void kernel_launch(void* const* d_in, const int* in_sizes, int n_in,
                              void* d_out, int out_size) {
    const float* x      = (const float*)d_in[0];
    const int*   ei     = (const int*)  d_in[1];
    const int*   batch  = (const int*)  d_in[2];
    const float* ea     = (const float*)d_in[3];
    const float* Wn     = (const float*)d_in[4];
    const float* bn     = (const float*)d_in[5];
    const float* We     = (const float*)d_in[6];
    const float* be     = (const float*)d_in[7];
    const float* eps    = (const float*)d_in[8];
    const float* mlp_W1 = (const float*)d_in[9];
    const float* mlp_b1 = (const float*)d_in[10];
    const float* mlp_W2 = (const float*)d_in[11];
    const float* mlp_b2 = (const float*)d_in[12];
    const float* bn_g   = (const float*)d_in[13];
    const float* bn_b   = (const float*)d_in[14];
    const float* cls_W1 = (const float*)d_in[15];
    const float* cls_b1 = (const float*)d_in[16];
    const float* cls_W2 = (const float*)d_in[17];
    const float* cls_b2 = (const float*)d_in[18];
    float* out = (float*)d_out;

    const int TPB = 256;
    const int node_blocks   = (N_NODES * HID + TPB - 1) / TPB;   // 12500
    const int node4_blocks  = (N_NODES * 16 + TPB - 1) / TPB;    // 3125
    const int edge16_blocks = (N_EDGES * 16) / TPB;              // 100000
    const int edge_blocks   = (N_EDGES + TPB - 1) / TPB;         // 6250
    const int mlp_blocks    = (N_NODES + MLP_TN - 1) / MLP_TN;   // 391
    const int mlp_smem      = (2 * HID * HID + HID * ZT_PAD + 4 * HID) * sizeof(float);

    static bool attr_set = false;
    if (!attr_set) {
        cudaFuncSetAttribute(k_mlp, cudaFuncAttributeMaxDynamicSharedMemorySize, mlp_smem);
        attr_set = true;
    }

    k_node_proj<<<node_blocks, TPB>>>(x, Wn, bn);    // also zeroes g_deg
    k_hist<<<edge_blocks, TPB>>>(ei);
    k_scan_part<<<N_CHUNKS, SCAN_CHUNK>>>();
    k_scan_top<<<1, 256>>>();
    k_scan_final<<<N_CHUNKS, SCAN_CHUNK>>>();
    k_scatter<<<edge_blocks, TPB>>>(ei);
    k_edge_proj<<<edge16_blocks, TPB>>>(ea, We, be);
    k_pool_zero<<<(N_GRAPHS * HID + TPB - 1) / TPB, TPB>>>();

    for (int l = 0; l < N_LAYERS; l++) {
        k_gather<<<node4_blocks, TPB>>>(eps, l);
        k_mlp<<<mlp_blocks, TPB, mlp_smem>>>(mlp_W1 + l * HID * HID, mlp_b1 + l * HID,
                                             mlp_W2 + l * HID * HID, mlp_b2 + l * HID);
        k_bnapply<<<node4_blocks, TPB>>>(bn_g + l * HID, bn_b + l * HID,
                                         batch, (l == N_LAYERS - 1) ? 1 : 0);
    }

    k_cls<<<N_GRAPHS, HID>>>(cls_W1, cls_b1, cls_W2, cls_b2, out);
}

// round 6
// speedup vs baseline: 1.9841x; 1.0373x over previous
#include <cuda_runtime.h>
#include <cuda_fp16.h>
#include <mma.h>
#include <cstdint>

using namespace nvcuda;

#define N_NODES   50000
#define N_EDGES   1600000
#define N_GRAPHS  128
#define IN_CH     64
#define EDGE_DIM  16
#define HID       64
#define N_CLASSES 10
#define N_LAYERS  5
#define BN_EPS    1e-5f

#define MLP_TN    128
#define LDT       72            // padded leading dim for smem tiles
#define SCAN_CHUNK 256
#define N_CHUNKS  ((N_NODES + SCAN_CHUNK - 1) / SCAN_CHUNK)   // 196

// ---------------- scratch (device globals) --------------------------------
__device__ __align__(16) float  g_h[N_NODES * HID];
__device__ __align__(16) __half g_h16[N_NODES * HID];           // fp16 mirror of h
__device__ __align__(16) float  g_z[N_NODES * HID];
__device__ __align__(16) float  g_zout[N_NODES * HID];
__device__ __align__(16) __half g_e16[(size_t)N_EDGES * HID];   // fp16 edge proj, CSR order
__device__ __align__(16) float  g_stats[2 * HID];
__device__ __align__(16) float  g_pool[N_GRAPHS * HID];
__device__ __align__(16) float  g_cnt[N_GRAPHS];
// CSR by dst
__device__ int  g_deg[N_NODES];
__device__ int  g_rowptr[N_NODES + 1];
__device__ int  g_cursor[N_NODES];
__device__ int  g_chunk[N_CHUNKS];
__device__ int  g_src[N_EDGES];     // src node per CSR slot
__device__ int  g_eorig[N_EDGES];   // original edge id per CSR slot

// ---------------- projections ---------------------------------------------

// h = x @ Wn + bn ; writes fp32 + fp16; zeroes g_deg.
__global__ void k_node_proj(const float* __restrict__ x,
                            const float* __restrict__ Wn,
                            const float* __restrict__ bn) {
    __shared__ float Ws[IN_CH * HID];
    __shared__ float bs[HID];
    int t = threadIdx.x;
    for (int i = t; i < IN_CH * HID; i += blockDim.x) Ws[i] = Wn[i];
    if (t < HID) bs[t] = bn[t];
    __syncthreads();
    int gid = blockIdx.x * blockDim.x + t;
    if (gid < N_NODES) g_deg[gid] = 0;
    if (gid >= N_NODES * HID) return;
    int n = gid >> 6, c = gid & 63;
    float acc = bs[c];
    const float* xr = x + (size_t)n * IN_CH;
#pragma unroll 16
    for (int k = 0; k < IN_CH; k++) acc += xr[k] * Ws[k * HID + c];
    g_h[gid] = acc;
    g_h16[gid] = __float2half(acc);
}

// e = edge_attr @ We + be -> fp16, iterating over CSR slots (coalesced writes).
__global__ void k_edge_proj(const float* __restrict__ ea,
                            const float* __restrict__ We,
                            const float* __restrict__ be) {
    __shared__ float Ws[EDGE_DIM * HID];
    __shared__ float bs[HID];
    int t = threadIdx.x;
    for (int i = t; i < EDGE_DIM * HID; i += blockDim.x) Ws[i] = We[i];
    if (t < HID) bs[t] = be[t];
    __syncthreads();
    int gid = blockIdx.x * blockDim.x + t;
    if (gid >= N_EDGES * 16) return;
    int slot = gid >> 4, q = gid & 15;
    int edge = g_eorig[slot];
    int c = q * 4;
    float a0 = bs[c], a1 = bs[c + 1], a2 = bs[c + 2], a3 = bs[c + 3];
    const float* er = ea + (size_t)edge * EDGE_DIM;
#pragma unroll
    for (int k = 0; k < EDGE_DIM; k++) {
        float v = er[k];
        const float4 w = *reinterpret_cast<const float4*>(&Ws[k * HID + c]);
        a0 += v * w.x; a1 += v * w.y; a2 += v * w.z; a3 += v * w.w;
    }
    __half2 p01 = __floats2half2_rn(a0, a1);
    __half2 p23 = __floats2half2_rn(a2, a3);
    uint2 pk;
    pk.x = *reinterpret_cast<unsigned*>(&p01);
    pk.y = *reinterpret_cast<unsigned*>(&p23);
    *reinterpret_cast<uint2*>(&g_e16[(size_t)slot * HID + c]) = pk;
}

// ---------------- CSR build ------------------------------------------------

__global__ void k_hist(const int* __restrict__ ei) {
    int e = blockIdx.x * blockDim.x + threadIdx.x;
    if (e >= N_EDGES) return;
    atomicAdd(&g_deg[ei[N_EDGES + e]], 1);
}

__global__ void k_scan_part() {
    __shared__ int sm[SCAN_CHUNK];
    int t = threadIdx.x;
    int idx = blockIdx.x * SCAN_CHUNK + t;
    int v = (idx < N_NODES) ? g_deg[idx] : 0;
    sm[t] = v;
    __syncthreads();
    for (int off = 128; off > 0; off >>= 1) {
        if (t < off) sm[t] += sm[t + off];
        __syncthreads();
    }
    if (t == 0) g_chunk[blockIdx.x] = sm[0];
}

__global__ void k_scan_top() {
    __shared__ int sm[256];
    int t = threadIdx.x;
    sm[t] = (t < N_CHUNKS) ? g_chunk[t] : 0;
    __syncthreads();
    for (int off = 1; off < 256; off <<= 1) {
        int v = (t >= off) ? sm[t - off] : 0;
        __syncthreads();
        sm[t] += v;
        __syncthreads();
    }
    if (t < N_CHUNKS) g_chunk[t] = (t > 0) ? sm[t - 1] : 0;
    if (t == 0) g_rowptr[N_NODES] = N_EDGES;
}

__global__ void k_scan_final() {
    __shared__ int sm[SCAN_CHUNK];
    int t = threadIdx.x;
    int idx = blockIdx.x * SCAN_CHUNK + t;
    int v = (idx < N_NODES) ? g_deg[idx] : 0;
    sm[t] = v;
    __syncthreads();
    for (int off = 1; off < SCAN_CHUNK; off <<= 1) {
        int u = (t >= off) ? sm[t - off] : 0;
        __syncthreads();
        sm[t] += u;
        __syncthreads();
    }
    if (idx < N_NODES) {
        int r = g_chunk[blockIdx.x] + sm[t] - v;   // exclusive
        g_rowptr[idx] = r;
        g_cursor[idx] = r;
    }
}

__global__ void k_scatter(const int* __restrict__ ei) {
    int e = blockIdx.x * blockDim.x + threadIdx.x;
    if (e >= N_EDGES) return;
    int src = ei[e];
    int dst = ei[N_EDGES + e];
    int pos = atomicAdd(&g_cursor[dst], 1);
    g_src[pos] = src;
    g_eorig[pos] = e;
}

// ---------------- per-layer kernels ----------------------------------------

// z[n] = (1+eps)*h[n] + sum_j relu(h16[src_j] + e16_j) ; unrolled x2.
__global__ void k_gather(const float* __restrict__ eps, int layer) {
    int t = threadIdx.x;
    if (blockIdx.x == 0 && t < 2 * HID) g_stats[t] = 0.0f;
    int gid = blockIdx.x * blockDim.x + t;
    if (gid >= N_NODES * 16) return;
    int node = gid >> 4;
    int c = (gid & 15) * 4;
    int j = g_rowptr[node];
    int end = g_rowptr[node + 1];
    float a0 = 0.f, a1 = 0.f, a2 = 0.f, a3 = 0.f;
    const __half2 zero2 = __float2half2_rn(0.0f);
    for (; j + 2 <= end; j += 2) {
        int s0 = g_src[j], s1 = g_src[j + 1];
        uint2 e0 = *reinterpret_cast<const uint2*>(&g_e16[(size_t)j * HID + c]);
        uint2 e1 = *reinterpret_cast<const uint2*>(&g_e16[(size_t)(j + 1) * HID + c]);
        uint2 h0 = *reinterpret_cast<const uint2*>(&g_h16[(size_t)s0 * HID + c]);
        uint2 h1 = *reinterpret_cast<const uint2*>(&g_h16[(size_t)s1 * HID + c]);
        __half2 m0a = __hmax2(__hadd2(*reinterpret_cast<__half2*>(&h0.x),
                                      *reinterpret_cast<__half2*>(&e0.x)), zero2);
        __half2 m0b = __hmax2(__hadd2(*reinterpret_cast<__half2*>(&h0.y),
                                      *reinterpret_cast<__half2*>(&e0.y)), zero2);
        __half2 m1a = __hmax2(__hadd2(*reinterpret_cast<__half2*>(&h1.x),
                                      *reinterpret_cast<__half2*>(&e1.x)), zero2);
        __half2 m1b = __hmax2(__hadd2(*reinterpret_cast<__half2*>(&h1.y),
                                      *reinterpret_cast<__half2*>(&e1.y)), zero2);
        float2 f0a = __half22float2(m0a), f0b = __half22float2(m0b);
        float2 f1a = __half22float2(m1a), f1b = __half22float2(m1b);
        a0 += f0a.x + f1a.x; a1 += f0a.y + f1a.y;
        a2 += f0b.x + f1b.x; a3 += f0b.y + f1b.y;
    }
    if (j < end) {
        int s0 = g_src[j];
        uint2 e0 = *reinterpret_cast<const uint2*>(&g_e16[(size_t)j * HID + c]);
        uint2 h0 = *reinterpret_cast<const uint2*>(&g_h16[(size_t)s0 * HID + c]);
        __half2 m0a = __hmax2(__hadd2(*reinterpret_cast<__half2*>(&h0.x),
                                      *reinterpret_cast<__half2*>(&e0.x)), zero2);
        __half2 m0b = __hmax2(__hadd2(*reinterpret_cast<__half2*>(&h0.y),
                                      *reinterpret_cast<__half2*>(&e0.y)), zero2);
        float2 f0a = __half22float2(m0a), f0b = __half22float2(m0b);
        a0 += f0a.x; a1 += f0a.y; a2 += f0b.x; a3 += f0b.y;
    }
    float se = 1.0f + eps[layer];
    float4 hv = *reinterpret_cast<const float4*>(&g_h[(size_t)node * HID + c]);
    float4 z = make_float4(se * hv.x + a0, se * hv.y + a1,
                           se * hv.z + a2, se * hv.w + a3);
    *reinterpret_cast<float4*>(&g_z[(size_t)node * HID + c]) = z;
}

// MLP on tensor cores (tf32). 128 nodes/block, 8 warps; warp w owns 16-node strip.
// zout = relu(z @ W1 + b1) @ W2 + b2 ; accumulates BN sum/sumsq.
__global__ void k_mlp_tc(const float* __restrict__ W1, const float* __restrict__ b1,
                         const float* __restrict__ W2, const float* __restrict__ b2) {
    extern __shared__ float sm[];
    float* zt   = sm;                      // [128][LDT]
    float* w1s  = zt + MLP_TN * LDT;       // [64][LDT]
    float* w2s  = w1s + HID * LDT;         // [64][LDT]
    float* b1s  = w2s + HID * LDT;
    float* b2s  = b1s + HID;
    float* ssum = b2s + HID;
    float* ssq  = ssum + HID;

    int t = threadIdx.x;
    for (int i = t; i < HID * HID; i += 256) {
        int r = i >> 6, c = i & 63;
        w1s[r * LDT + c] = W1[i];
        w2s[r * LDT + c] = W2[i];
    }
    if (t < HID) { b1s[t] = b1[t]; b2s[t] = b2[t]; ssum[t] = 0.0f; ssq[t] = 0.0f; }
    int node0 = blockIdx.x * MLP_TN;

    for (int i = t; i < MLP_TN * 16; i += 256) {
        int n = i >> 4, kc = (i & 15) * 4;
        int node = node0 + n;
        float4 zv = make_float4(0.f, 0.f, 0.f, 0.f);
        if (node < N_NODES)
            zv = *reinterpret_cast<const float4*>(&g_z[(size_t)node * HID + kc]);
        *reinterpret_cast<float4*>(&zt[n * LDT + kc]) = zv;
    }
    __syncthreads();

    int warp = t >> 5, lane = t & 31;
    float* arow = zt + warp * 16 * LDT;    // this warp's 16-row strip

    // ---- GEMM1: strip @ W1 ----
    wmma::fragment<wmma::accumulator, 16, 16, 8, float> cf[4];
#pragma unroll
    for (int nt = 0; nt < 4; nt++) wmma::fill_fragment(cf[nt], 0.0f);
#pragma unroll
    for (int k = 0; k < HID; k += 8) {
        wmma::fragment<wmma::matrix_a, 16, 16, 8, wmma::precision::tf32, wmma::row_major> af;
        wmma::load_matrix_sync(af, arow + k, LDT);
#pragma unroll
        for (int i = 0; i < af.num_elements; i++) af.x[i] = wmma::__float_to_tf32(af.x[i]);
#pragma unroll
        for (int nt = 0; nt < 4; nt++) {
            wmma::fragment<wmma::matrix_b, 16, 16, 8, wmma::precision::tf32, wmma::row_major> bf;
            wmma::load_matrix_sync(bf, w1s + k * LDT + nt * 16, LDT);
#pragma unroll
            for (int i = 0; i < bf.num_elements; i++) bf.x[i] = wmma::__float_to_tf32(bf.x[i]);
            wmma::mma_sync(cf[nt], af, bf, cf[nt]);
        }
    }
#pragma unroll
    for (int nt = 0; nt < 4; nt++)
        wmma::store_matrix_sync(arow + nt * 16, cf[nt], LDT, wmma::mem_row_major);
    __syncwarp();
    // bias + relu on strip
    for (int i = lane; i < 16 * HID; i += 32) {
        int r = i >> 6, c = i & 63;
        arow[r * LDT + c] = fmaxf(arow[r * LDT + c] + b1s[c], 0.0f);
    }
    __syncwarp();

    // ---- GEMM2: strip @ W2 ----
#pragma unroll
    for (int nt = 0; nt < 4; nt++) wmma::fill_fragment(cf[nt], 0.0f);
#pragma unroll
    for (int k = 0; k < HID; k += 8) {
        wmma::fragment<wmma::matrix_a, 16, 16, 8, wmma::precision::tf32, wmma::row_major> af;
        wmma::load_matrix_sync(af, arow + k, LDT);
#pragma unroll
        for (int i = 0; i < af.num_elements; i++) af.x[i] = wmma::__float_to_tf32(af.x[i]);
#pragma unroll
        for (int nt = 0; nt < 4; nt++) {
            wmma::fragment<wmma::matrix_b, 16, 16, 8, wmma::precision::tf32, wmma::row_major> bf;
            wmma::load_matrix_sync(bf, w2s + k * LDT + nt * 16, LDT);
#pragma unroll
            for (int i = 0; i < bf.num_elements; i++) bf.x[i] = wmma::__float_to_tf32(bf.x[i]);
            wmma::mma_sync(cf[nt], af, bf, cf[nt]);
        }
    }
#pragma unroll
    for (int nt = 0; nt < 4; nt++)
        wmma::store_matrix_sync(arow + nt * 16, cf[nt], LDT, wmma::mem_row_major);
    __syncwarp();

    // bias + write global + per-column stats (column c = lane, lane+32)
#pragma unroll
    for (int half = 0; half < 2; half++) {
        int c = lane + half * 32;
        float s = 0.f, q = 0.f;
#pragma unroll
        for (int r = 0; r < 16; r++) {
            int node = node0 + warp * 16 + r;
            if (node < N_NODES) {
                float v = arow[r * LDT + c] + b2s[c];
                g_zout[(size_t)node * HID + c] = v;
                s += v; q += v * v;
            }
        }
        atomicAdd(&ssum[c], s);
        atomicAdd(&ssq[c], q);
    }
    __syncthreads();
    if (t < HID) {
        atomicAdd(&g_stats[t], ssum[t]);
        atomicAdd(&g_stats[HID + t], ssq[t]);
    }
}

// h = relu(gamma*(zout - mu)*inv_std + beta) + h ; writes fp32 + fp16 h.
// If last layer, fuse pooling.
__global__ void k_bnapply(const float* __restrict__ gamma,
                          const float* __restrict__ beta,
                          const int* __restrict__ batch, int do_pool) {
    int gid = blockIdx.x * blockDim.x + threadIdx.x;
    if (gid >= N_NODES * 16) return;
    int c = (gid & 15) * 4;
    const float invN = 1.0f / (float)N_NODES;
    float4 v = *reinterpret_cast<const float4*>(&g_zout[(size_t)gid * 4]);
    float4 h = *reinterpret_cast<const float4*>(&g_h[(size_t)gid * 4]);
    float r[4] = {v.x, v.y, v.z, v.w};
    float hh[4] = {h.x, h.y, h.z, h.w};
#pragma unroll
    for (int j = 0; j < 4; j++) {
        float mu = g_stats[c + j] * invN;
        float var = g_stats[HID + c + j] * invN - mu * mu;
        float inv = rsqrtf(var + BN_EPS);
        float tt = gamma[c + j] * (r[j] - mu) * inv + beta[c + j];
        r[j] = fmaxf(tt, 0.0f) + hh[j];
    }
    *reinterpret_cast<float4*>(&g_h[(size_t)gid * 4]) = make_float4(r[0], r[1], r[2], r[3]);
    __half2 p01 = __floats2half2_rn(r[0], r[1]);
    __half2 p23 = __floats2half2_rn(r[2], r[3]);
    uint2 pk;
    pk.x = *reinterpret_cast<unsigned*>(&p01);
    pk.y = *reinterpret_cast<unsigned*>(&p23);
    *reinterpret_cast<uint2*>(&g_h16[(size_t)gid * 4]) = pk;
    if (do_pool) {
        int n = gid >> 4;
        int b = batch[n];
        float* p = &g_pool[b * HID + c];
        asm volatile("red.global.add.v4.f32 [%0], {%1, %2, %3, %4};"
                     :: "l"(p), "f"(r[0]), "f"(r[1]), "f"(r[2]), "f"(r[3]) : "memory");
        if ((gid & 15) == 0)
            asm volatile("red.global.add.f32 [%0], %1;" :: "l"(&g_cnt[b]), "f"(1.0f) : "memory");
    }
}

// ---------------- pooling + classifier -------------------------------------

__global__ void k_pool_zero() {
    int gid = blockIdx.x * blockDim.x + threadIdx.x;
    if (gid < N_GRAPHS * HID) g_pool[gid] = 0.0f;
    if (gid < N_GRAPHS) g_cnt[gid] = 0.0f;
}

// classifier: one block (64 threads) per graph
__global__ void k_cls(const float* __restrict__ W1, const float* __restrict__ b1,
                      const float* __restrict__ W2, const float* __restrict__ b2,
                      float* __restrict__ out) {
    __shared__ float pr[HID];
    __shared__ float aw[HID];
    int g = blockIdx.x;
    int t = threadIdx.x;
    float cnt = fmaxf(g_cnt[g], 1.0f);
    pr[t] = g_pool[g * HID + t] / cnt;
    __syncthreads();
    float acc = b1[t];
#pragma unroll 8
    for (int k = 0; k < HID; k++) acc += pr[k] * W1[k * HID + t];
    aw[t] = fmaxf(acc, 0.0f);
    __syncthreads();
    if (t < N_CLASSES) {
        float o = b2[t];
#pragma unroll 8
        for (int k = 0; k < HID; k++) o += aw[k] * W2[k * N_CLASSES + t];
        float prob = 1.0f / (1.0f + expf(-o));
        float pred = (prob > 0.5f) ? 1.0f : 0.0f;
        int idx = g * N_CLASSES + t;
        out[idx] = o;
        out[N_GRAPHS * N_CLASSES + idx] = prob;
        out[2 * N_GRAPHS * N_CLASSES + idx] = pred;
        out[3 * N_GRAPHS * N_CLASSES + idx] = pred;
    }
}

// ---------------- launch --------------------------------------------------
extern "C" void kernel_launch(void* const* d_in, const int* in_sizes, int n_in,
                              void* d_out, int out_size) {
    const float* x      = (const float*)d_in[0];
    const int*   ei     = (const int*)  d_in[1];
    const int*   batch  = (const int*)  d_in[2];
    const float* ea     = (const float*)d_in[3];
    const float* Wn     = (const float*)d_in[4];
    const float* bn     = (const float*)d_in[5];
    const float* We     = (const float*)d_in[6];
    const float* be     = (const float*)d_in[7];
    const float* eps    = (const float*)d_in[8];
    const float* mlp_W1 = (const float*)d_in[9];
    const float* mlp_b1 = (const float*)d_in[10];
    const float* mlp_W2 = (const float*)d_in[11];
    const float* mlp_b2 = (const float*)d_in[12];
    const float* bn_g   = (const float*)d_in[13];
    const float* bn_b   = (const float*)d_in[14];
    const float* cls_W1 = (const float*)d_in[15];
    const float* cls_b1 = (const float*)d_in[16];
    const float* cls_W2 = (const float*)d_in[17];
    const float* cls_b2 = (const float*)d_in[18];
    float* out = (float*)d_out;

    const int TPB = 256;
    const int node_blocks   = (N_NODES * HID + TPB - 1) / TPB;   // 12500
    const int node4_blocks  = (N_NODES * 16 + TPB - 1) / TPB;    // 3125
    const int edge16_blocks = (N_EDGES * 16) / TPB;              // 100000
    const int edge_blocks   = (N_EDGES + TPB - 1) / TPB;         // 6250
    const int mlp_blocks    = (N_NODES + MLP_TN - 1) / MLP_TN;   // 391
    const int mlp_smem      = (MLP_TN * LDT + 2 * HID * LDT + 4 * HID) * sizeof(float);

    static bool attr_set = false;
    if (!attr_set) {
        cudaFuncSetAttribute(k_mlp_tc, cudaFuncAttributeMaxDynamicSharedMemorySize, mlp_smem);
        attr_set = true;
    }

    k_node_proj<<<node_blocks, TPB>>>(x, Wn, bn);    // also zeroes g_deg
    k_hist<<<edge_blocks, TPB>>>(ei);
    k_scan_part<<<N_CHUNKS, SCAN_CHUNK>>>();
    k_scan_top<<<1, 256>>>();
    k_scan_final<<<N_CHUNKS, SCAN_CHUNK>>>();
    k_scatter<<<edge_blocks, TPB>>>(ei);
    k_edge_proj<<<edge16_blocks, TPB>>>(ea, We, be);
    k_pool_zero<<<(N_GRAPHS * HID + TPB - 1) / TPB, TPB>>>();

    for (int l = 0; l < N_LAYERS; l++) {
        k_gather<<<node4_blocks, TPB>>>(eps, l);
        k_mlp_tc<<<mlp_blocks, TPB, mlp_smem>>>(mlp_W1 + l * HID * HID, mlp_b1 + l * HID,
                                                mlp_W2 + l * HID * HID, mlp_b2 + l * HID);
        k_bnapply<<<node4_blocks, TPB>>>(bn_g + l * HID, bn_b + l * HID,
                                         batch, (l == N_LAYERS - 1) ? 1 : 0);
    }

    k_cls<<<N_GRAPHS, HID>>>(cls_W1, cls_b1, cls_W2, cls_b2, out);
}